// round 1
// baseline (speedup 1.0000x reference)
#include <cuda_runtime.h>

#define NROWS 32768
#define DCOLS 2048
#define EPS 1e-6f

// Scratch (allocation-free rule: __device__ globals)
__device__ float g_u[DCOLS];
__device__ float g_s[DCOLS];

// ---------------------------------------------------------------------------
// 1) zero the accumulator (must happen every replay)
__global__ void zero_u_kernel() {
    int i = blockIdx.x * blockDim.x + threadIdx.x;
    if (i < DCOLS) g_u[i] = 0.0f;
}

// ---------------------------------------------------------------------------
// 2) column sum-of-squares reduction.
// grid = (DCOLS/1024, ROW_CHUNKS), block = 256 threads.
// Each thread owns 4 consecutive columns (one float4 lane) and walks
// ROWS_PER_CHUNK rows; coalesced 128B lines per warp.
#define ROW_CHUNKS 256
#define ROWS_PER_CHUNK (NROWS / ROW_CHUNKS)   // 128

__global__ void __launch_bounds__(256) reduce_kernel(const float* __restrict__ x) {
    const int col4 = blockIdx.x * blockDim.x + threadIdx.x;   // 0..511
    const int r0   = blockIdx.y * ROWS_PER_CHUNK;
    const float4* __restrict__ xv = (const float4*)x;

    float ax = 0.f, ay = 0.f, az = 0.f, aw = 0.f;
    size_t base = (size_t)r0 * (DCOLS / 4) + col4;

#pragma unroll 8
    for (int r = 0; r < ROWS_PER_CHUNK; ++r) {
        float4 v = xv[base + (size_t)r * (DCOLS / 4)];
        ax = fmaf(v.x, v.x, ax);
        ay = fmaf(v.y, v.y, ay);
        az = fmaf(v.z, v.z, az);
        aw = fmaf(v.w, v.w, aw);
    }

    float* u = &g_u[col4 * 4];
    atomicAdd(u + 0, ax);
    atomicAdd(u + 1, ay);
    atomicAdd(u + 2, az);
    atomicAdd(u + 3, aw);
}

// ---------------------------------------------------------------------------
// 3) s = rsqrt(u + eps)  (tiny; keeps MUFU out of the hot loop)
__global__ void rsqrt_kernel() {
    int i = blockIdx.x * blockDim.x + threadIdx.x;
    if (i < DCOLS) g_s[i] = rsqrtf(g_u[i] + EPS);
}

// ---------------------------------------------------------------------------
// 4) y = x * s[col]. One float4 per thread; s float4 load hits L1 (8 KB total).
__global__ void __launch_bounds__(256) scale_kernel(const float* __restrict__ x,
                                                    float* __restrict__ y) {
    const size_t i = (size_t)blockIdx.x * blockDim.x + threadIdx.x;  // float4 index
    const int c = (int)(i & (DCOLS / 4 - 1));                        // 0..511
    const float4* __restrict__ xv = (const float4*)x;
    const float4* __restrict__ sv = (const float4*)g_s;
    float4* __restrict__ yv = (float4*)y;

    float4 v = xv[i];
    float4 s = sv[c];
    v.x *= s.x;
    v.y *= s.y;
    v.z *= s.z;
    v.w *= s.w;
    yv[i] = v;
}

// ---------------------------------------------------------------------------
extern "C" void kernel_launch(void* const* d_in, const int* in_sizes, int n_in,
                              void* d_out, int out_size) {
    const float* x = (const float*)d_in[0];
    float* y = (float*)d_out;

    zero_u_kernel<<<(DCOLS + 255) / 256, 256>>>();

    dim3 rgrid(DCOLS / 1024, ROW_CHUNKS);   // (2, 256)
    reduce_kernel<<<rgrid, 256>>>(x);

    rsqrt_kernel<<<(DCOLS + 255) / 256, 256>>>();

    const size_t total4 = (size_t)NROWS * DCOLS / 4;   // 16,777,216
    scale_kernel<<<(unsigned)(total4 / 256), 256>>>(x, y);
}